// round 5
// baseline (speedup 1.0000x reference)
#include <cuda_runtime.h>
#include <stdint.h>

// PicMix: output = two index-function masks, no input read.
// Flattened: [mask_a (8,12,512,512) fp32][mask_b same]. 192 planes of 512x512.
// group g = (ch%12)/3; isB = second mask.
//   g0: a=1,b=0 | g1: a=(i%2==j%2) | g2: a=i%2 | g3: a=j%2 ; b = complement.
// Each float4 covers j..j+3 (even start) -> lanes are (even,odd,even,odd).
//
// R5: parallelism-sweep midpoint — 24576 CTAs x 256 thr x 2 float4/thread.
// Thread stride = 256 f4 = exactly 2 rows, so row parity (and the store
// value) is constant per thread; decode once, 2x STG.E.128 at immediate
// offsets. Branch-free value decode.

static constexpr int PLANE_F4         = 65536;  // 512*512/4
static constexpr int BLOCKS_PER_PLANE = 128;
static constexpr int F4_PER_BLOCK     = PLANE_F4 / BLOCKS_PER_PLANE; // 512
static constexpr int THREADS          = 256;
static constexpr int F4_PER_THREAD    = F4_PER_BLOCK / THREADS;      // 2

__global__ void __launch_bounds__(THREADS) picmix_kernel(float4* __restrict__ out) {
    int plane = blockIdx.x >> 7;        // BLOCKS_PER_PLANE = 128
    int seg   = blockIdx.x & 127;

    int base = plane * PLANE_F4 + seg * F4_PER_BLOCK + threadIdx.x;
    int ip   = (base >> 7) & 1;         // row parity; invariant across both stores

    int isB = plane >= 96;              // 96 planes per mask
    int pin = plane - (isB ? 96 : 0);
    int ch  = pin - (pin * 0x2AAB >> 17) * 12;   // pin % 12 (pin < 96)
    int g   = ch * 0x5556 >> 16;                 // ch / 3

    // Branch-free even/odd lane values for mask_a, then complement for mask_b.
    // g0: e=1,o=1 | g1: e=!ip,o=ip | g2: e=ip,o=ip | g3: e=0,o=1
    int e_a = (g == 0) | ((g == 1) & (ip == 0)) | ((g == 2) & ip);
    int o_a = (g == 0) | ((g == 1) & ip) | ((g == 2) & ip) | (g == 3);
    int zeroComp = (g == 0);            // for g0, mask_b is all-zero (not 1-a)

    float e, o;
    if (isB) {
        e = zeroComp ? 0.0f : (float)(1 - e_a);
        o = zeroComp ? 0.0f : (float)(1 - o_a);
    } else {
        e = (float)e_a;
        o = (float)o_a;
    }

    float4 v4 = make_float4(e, o, e, o);
    float4* p = out + base;
    p[0]       = v4;                    // stride 256 f4 = 4KB = 2 rows
    p[THREADS] = v4;
}

extern "C" void kernel_launch(void* const* d_in, const int* in_sizes, int n_in,
                              void* d_out, int out_size) {
    (void)d_in; (void)in_sizes; (void)n_in; (void)out_size;
    // out_size = 50,331,648 fp32 = 192 planes * 65536 f4
    int blocks = 192 * BLOCKS_PER_PLANE;  // 24576
    picmix_kernel<<<blocks, THREADS>>>((float4*)d_out);
}